// round 1
// baseline (speedup 1.0000x reference)
#include <cuda_runtime.h>
#include <cuda_bf16.h>
#include <math.h>

// Problem constants (fixed by setup_inputs)
#define BATCH 2
#define SEQ   2048
#define EMB   1024
#define NHEAD 16
#define HDIM  64
#define M_ROWS (BATCH*SEQ)      // 4096
#define QKV_N  (3*EMB)          // 3072

// ---------------- scratch (device globals, no allocation) ----------------
__device__ float g_T[HDIM*HDIM];                 // 64x64 folded transform
__device__ float g_Wf[EMB*QKV_N];                // folded QKV weights
__device__ float g_bf[QKV_N];                    // folded QKV bias
__device__ float g_qkv[(size_t)M_ROWS*QKV_N];    // QKV activations (50 MB)
__device__ float g_attn[(size_t)M_ROWS*EMB];     // attention output (16 MB)

// ---------------- build T = I + (alpha/64) * H diag H --------------------
__global__ void build_T_kernel(const float* __restrict__ diag,
                               const float* __restrict__ alpha_p) {
    int i = blockIdx.x;    // 0..63
    int j = threadIdx.x;   // 0..63
    float a = alpha_p[0] * (1.0f / 64.0f);
    int ij = i ^ j;
    float acc = 0.f;
    #pragma unroll
    for (int k = 0; k < 64; k++) {
        float s = (__popc(ij & k) & 1) ? -1.f : 1.f;
        acc += diag[k] * s;
    }
    g_T[i*64 + j] = a * acc + ((i == j) ? 1.f : 0.f);
}

// ---------------- fold T into QKV weights --------------------------------
// q,k column blocks (cols [0,2048)): W'[e, base+j] = sum_d W[e, base+d]*T[d][j]
// v block copied unchanged.
__global__ void fold_w_kernel(const float* __restrict__ W) {
    int c = blockIdx.x * blockDim.x + threadIdx.x;   // 0..3071
    int e = blockIdx.y;                              // 0..1023
    if (c >= QKV_N) return;
    size_t row = (size_t)e * QKV_N;
    if (c < 2*EMB) {
        int j = c & 63;
        int base = c - j;
        float acc = 0.f;
        #pragma unroll 8
        for (int d = 0; d < 64; d++)
            acc += W[row + base + d] * g_T[d*64 + j];
        g_Wf[row + c] = acc;
    } else {
        g_Wf[row + c] = W[row + c];
    }
}

__global__ void fold_b_kernel(const float* __restrict__ bqkv,
                              const float* __restrict__ bias_h) {
    int c = blockIdx.x * blockDim.x + threadIdx.x;
    if (c >= QKV_N) return;
    if (c < 2*EMB) {
        int j = c & 63;
        int base = c - j;
        float acc = bias_h[j];
        #pragma unroll 8
        for (int d = 0; d < 64; d++)
            acc += bqkv[base + d] * g_T[d*64 + j];
        g_bf[c] = acc;
    } else {
        g_bf[c] = bqkv[c];
    }
}

// ---------------- tiled fp32 SGEMM with bias: C = A@B + bias -------------
// 64x64 output tile, 16x16 threads, 4x4 microtile, K-step 16.
__global__ void sgemm_bias_kernel(const float* __restrict__ A,
                                  const float* __restrict__ B,
                                  const float* __restrict__ bias,
                                  float* __restrict__ C,
                                  int M, int N, int K) {
    __shared__ float As[16][64];
    __shared__ float Bs[16][64];
    int tid = threadIdx.x;
    int tx = tid & 15, ty = tid >> 4;
    int n0 = blockIdx.x * 64;
    int m0 = blockIdx.y * 64;

    float acc[4][4];
    #pragma unroll
    for (int i = 0; i < 4; i++)
        #pragma unroll
        for (int j = 0; j < 4; j++) acc[i][j] = 0.f;

    for (int k0 = 0; k0 < K; k0 += 16) {
        // A tile: As[k][m]
        #pragma unroll
        for (int idx = tid; idx < 1024; idx += 256) {
            int mm = idx >> 4, kk = idx & 15;
            As[kk][mm] = A[(size_t)(m0 + mm) * K + (k0 + kk)];
        }
        // B tile: Bs[k][n]
        #pragma unroll
        for (int idx = tid; idx < 1024; idx += 256) {
            int kk = idx >> 6, nn = idx & 63;
            Bs[kk][nn] = B[(size_t)(k0 + kk) * N + (n0 + nn)];
        }
        __syncthreads();
        #pragma unroll
        for (int kk = 0; kk < 16; kk++) {
            float a[4], b[4];
            #pragma unroll
            for (int i = 0; i < 4; i++) a[i] = As[kk][ty*4 + i];
            #pragma unroll
            for (int j = 0; j < 4; j++) b[j] = Bs[kk][tx*4 + j];
            #pragma unroll
            for (int i = 0; i < 4; i++)
                #pragma unroll
                for (int j = 0; j < 4; j++)
                    acc[i][j] += a[i] * b[j];
        }
        __syncthreads();
    }
    #pragma unroll
    for (int i = 0; i < 4; i++) {
        size_t orow = (size_t)(m0 + ty*4 + i) * N + n0;
        #pragma unroll
        for (int j = 0; j < 4; j++)
            C[orow + tx*4 + j] = acc[i][j] + bias[n0 + tx*4 + j];
    }
}

// ---------------- flash-attention (fp32, D=64) ----------------------------
// Block: one (b,h) and a 64-query tile. 256 threads (16x16), 4x4 microtiles.
// Streams 64-key tiles with online softmax. P reuses K's smem buffer.
#define QS_PITCH 65
__global__ void attn_kernel(const float* __restrict__ qkv,
                            const int* __restrict__ mask,
                            float* __restrict__ out) {
    extern __shared__ float sm[];
    float* Qs = sm;                       // 64*65
    float* Ks = sm + 64*QS_PITCH;         // 64*65 (also holds P)
    float* Vs = Ks + 64*QS_PITCH;         // 64*65

    int bh = blockIdx.x;
    int b  = bh >> 4;
    int h  = bh & 15;
    int q0 = blockIdx.y * 64;

    int tid = threadIdx.x;
    int tx = tid & 15, ty = tid >> 4;

    const size_t rs = QKV_N;  // row stride in qkv
    const float* qbase = qkv + (size_t)(b*SEQ)*rs + h*HDIM;
    const float* kbase = qbase + EMB;
    const float* vbase = qbase + 2*EMB;
    const int*   mrow  = mask + b*SEQ;

    // load Q tile
    for (int idx = tid; idx < 64*64; idx += 256) {
        int r = idx >> 6, d = idx & 63;
        Qs[r*QS_PITCH + d] = qbase[(size_t)(q0 + r)*rs + d];
    }

    float o[4][4];
    float m[4], l[4];
    #pragma unroll
    for (int i = 0; i < 4; i++) {
        m[i] = -1e30f; l[i] = 0.f;
        #pragma unroll
        for (int j = 0; j < 4; j++) o[i][j] = 0.f;
    }

    for (int k0 = 0; k0 < SEQ; k0 += 64) {
        __syncthreads();  // previous iter's P/V reads complete
        for (int idx = tid; idx < 64*64; idx += 256) {
            int c = idx >> 6, d = idx & 63;
            Ks[c*QS_PITCH + d] = kbase[(size_t)(k0 + c)*rs + d];
            Vs[c*QS_PITCH + d] = vbase[(size_t)(k0 + c)*rs + d];
        }
        __syncthreads();

        // S = Q K^T * 0.125
        float s[4][4];
        #pragma unroll
        for (int i = 0; i < 4; i++)
            #pragma unroll
            for (int j = 0; j < 4; j++) s[i][j] = 0.f;
        #pragma unroll 4
        for (int d = 0; d < 64; d++) {
            float qv[4], kv[4];
            #pragma unroll
            for (int i = 0; i < 4; i++) qv[i] = Qs[(ty*4 + i)*QS_PITCH + d];
            #pragma unroll
            for (int j = 0; j < 4; j++) kv[j] = Ks[(tx*4 + j)*QS_PITCH + d];
            #pragma unroll
            for (int i = 0; i < 4; i++)
                #pragma unroll
                for (int j = 0; j < 4; j++)
                    s[i][j] += qv[i] * kv[j];
        }
        // scale + mask
        #pragma unroll
        for (int j = 0; j < 4; j++) {
            int mv = mrow[k0 + tx*4 + j];
            #pragma unroll
            for (int i = 0; i < 4; i++)
                s[i][j] = mv ? s[i][j] * 0.125f : -1e30f;
        }
        // online softmax update per row (rows replicated across the 16 tx lanes)
        #pragma unroll
        for (int i = 0; i < 4; i++) {
            float rm = fmaxf(fmaxf(s[i][0], s[i][1]), fmaxf(s[i][2], s[i][3]));
            #pragma unroll
            for (int off = 1; off < 16; off <<= 1)
                rm = fmaxf(rm, __shfl_xor_sync(0xffffffffu, rm, off));
            float mn = fmaxf(m[i], rm);
            float sc = __expf(m[i] - mn);
            m[i] = mn;
            l[i] *= sc;
            #pragma unroll
            for (int j = 0; j < 4; j++) o[i][j] *= sc;
            float rsum = 0.f;
            #pragma unroll
            for (int j = 0; j < 4; j++) {
                float p = __expf(s[i][j] - mn);
                s[i][j] = p;
                rsum += p;
            }
            #pragma unroll
            for (int off = 1; off < 16; off <<= 1)
                rsum += __shfl_xor_sync(0xffffffffu, rsum, off);
            l[i] += rsum;
        }
        __syncthreads();  // all K reads done before overwriting with P
        #pragma unroll
        for (int i = 0; i < 4; i++)
            #pragma unroll
            for (int j = 0; j < 4; j++)
                Ks[(ty*4 + i)*QS_PITCH + tx*4 + j] = s[i][j];
        __syncthreads();

        // O += P @ V
        #pragma unroll 4
        for (int c = 0; c < 64; c++) {
            float vv[4];
            #pragma unroll
            for (int j = 0; j < 4; j++) vv[j] = Vs[c*QS_PITCH + tx*4 + j];
            #pragma unroll
            for (int i = 0; i < 4; i++) {
                float pv = Ks[(ty*4 + i)*QS_PITCH + c];
                #pragma unroll
                for (int j = 0; j < 4; j++) o[i][j] += pv * vv[j];
            }
        }
    }

    // epilogue: normalize and write [b, q, h*64+d]
    #pragma unroll
    for (int i = 0; i < 4; i++) {
        float inv = 1.f / l[i];
        size_t orow = (size_t)(b*SEQ + q0 + ty*4 + i) * EMB + h*HDIM;
        #pragma unroll
        for (int j = 0; j < 4; j++)
            out[orow + tx*4 + j] = o[i][j] * inv;
    }
}

// ---------------- launch ---------------------------------------------------
extern "C" void kernel_launch(void* const* d_in, const int* in_sizes, int n_in,
                              void* d_out, int out_size) {
    const float* x      = (const float*)d_in[0];
    const int*   mask   = (const int*)  d_in[1];
    const float* Wqkv   = (const float*)d_in[2];
    const float* bqkv   = (const float*)d_in[3];
    const float* Wout   = (const float*)d_in[4];
    const float* bout   = (const float*)d_in[5];
    const float* diag   = (const float*)d_in[6];
    const float* alpha  = (const float*)d_in[7];
    const float* bias_h = (const float*)d_in[8];
    float* out = (float*)d_out;

    float* qkv;  cudaGetSymbolAddress((void**)&qkv,  g_qkv);
    float* attn; cudaGetSymbolAddress((void**)&attn, g_attn);
    float* Wf;   cudaGetSymbolAddress((void**)&Wf,   g_Wf);
    float* bf;   cudaGetSymbolAddress((void**)&bf,   g_bf);

    // 1. 64x64 transform matrix
    build_T_kernel<<<64, 64>>>(diag, alpha);

    // 2. fold transform into QKV weights + bias
    {
        dim3 grid((QKV_N + 255)/256, EMB);
        fold_w_kernel<<<grid, 256>>>(Wqkv);
        fold_b_kernel<<<(QKV_N + 255)/256, 256>>>(bqkv, bias_h);
    }

    // 3. QKV GEMM: [4096,1024] @ [1024,3072]
    {
        dim3 grid(QKV_N/64, M_ROWS/64);
        sgemm_bias_kernel<<<grid, 256>>>(x, Wf, bf, qkv, M_ROWS, QKV_N, EMB);
    }

    // 4. attention
    {
        size_t smem = (size_t)3 * 64 * QS_PITCH * sizeof(float);  // 49920 B
        cudaFuncSetAttribute(attn_kernel,
                             cudaFuncAttributeMaxDynamicSharedMemorySize,
                             (int)smem);
        dim3 grid(BATCH*NHEAD, SEQ/64);
        attn_kernel<<<grid, 256, smem>>>(qkv, mask, attn);
    }

    // 5. output projection: [4096,1024] @ [1024,1024]
    {
        dim3 grid(EMB/64, M_ROWS/64);
        sgemm_bias_kernel<<<grid, 256>>>(attn, Wout, bout, out,
                                         M_ROWS, EMB, EMB);
    }
}

// round 2
// speedup vs baseline: 3.6479x; 3.6479x over previous
#include <cuda_runtime.h>
#include <cuda_bf16.h>
#include <math.h>

#define BATCH 2
#define SEQ   2048
#define EMB   1024
#define NHEAD 16
#define HDIM  64
#define M_ROWS (BATCH*SEQ)      // 4096
#define QKV_N  (3*EMB)          // 3072

// ---------------- scratch (device globals, no allocation) ----------------
__device__ float g_T[HDIM*HDIM];
__device__ float g_Wf[EMB*QKV_N];
__device__ float g_bf[QKV_N];
__device__ float g_qkv[(size_t)M_ROWS*QKV_N];
__device__ float g_attn[(size_t)M_ROWS*EMB];

__device__ __forceinline__ unsigned f2tf(float f) {
    unsigned u;
    asm("cvt.rna.tf32.f32 %0, %1;" : "=r"(u) : "f"(f));
    return u;
}

__device__ __forceinline__ void mma_tf32(float c[4],
                                         unsigned a0, unsigned a1, unsigned a2, unsigned a3,
                                         unsigned b0, unsigned b1) {
    asm volatile(
        "mma.sync.aligned.m16n8k8.row.col.f32.tf32.tf32.f32 "
        "{%0,%1,%2,%3}, {%4,%5,%6,%7}, {%8,%9}, {%0,%1,%2,%3};"
        : "+f"(c[0]), "+f"(c[1]), "+f"(c[2]), "+f"(c[3])
        : "r"(a0), "r"(a1), "r"(a2), "r"(a3), "r"(b0), "r"(b1));
}

// ---------------- build T = I + (alpha/64) * H diag H --------------------
__global__ void build_T_kernel(const float* __restrict__ diag,
                               const float* __restrict__ alpha_p) {
    int i = blockIdx.x, j = threadIdx.x;
    float a = alpha_p[0] * (1.0f / 64.0f);
    int ij = i ^ j;
    float acc = 0.f;
    #pragma unroll
    for (int k = 0; k < 64; k++)
        acc += diag[k] * ((__popc(ij & k) & 1) ? -1.f : 1.f);
    g_T[i*64 + j] = a * acc + ((i == j) ? 1.f : 0.f);
}

// ---------------- fold T into QKV weights --------------------------------
__global__ void fold_w_kernel(const float* __restrict__ W) {
    int c = blockIdx.x * blockDim.x + threadIdx.x;
    int e = blockIdx.y;
    if (c >= QKV_N) return;
    size_t row = (size_t)e * QKV_N;
    if (c < 2*EMB) {
        int j = c & 63;
        int base = c - j;
        float acc = 0.f;
        #pragma unroll 8
        for (int d = 0; d < 64; d++)
            acc += W[row + base + d] * g_T[d*64 + j];
        g_Wf[row + c] = acc;
    } else {
        g_Wf[row + c] = W[row + c];
    }
}

__global__ void fold_b_kernel(const float* __restrict__ bqkv,
                              const float* __restrict__ bias_h) {
    int c = blockIdx.x * blockDim.x + threadIdx.x;
    if (c >= QKV_N) return;
    if (c < 2*EMB) {
        int j = c & 63;
        int base = c - j;
        float acc = bias_h[j];
        #pragma unroll 8
        for (int d = 0; d < 64; d++)
            acc += bqkv[base + d] * g_T[d*64 + j];
        g_bf[c] = acc;
    } else {
        g_bf[c] = bqkv[c];
    }
}

// ---------------- tf32 tensor-core GEMM: C = A@B + bias ------------------
// 128x128 block tile, 256 threads = 8 warps (2 along M x 4 along N),
// warp tile 64x32, m16n8k8 fragments, BK=16, double-buffered smem.
#define BPITCH 136   // 128 + 8 pad: bank = (8k + n) % 32, conflict-free frag reads
__global__ __launch_bounds__(256)
void gemm_tf32_kernel(const float* __restrict__ A,
                      const float* __restrict__ B,
                      const float* __restrict__ bias,
                      float* __restrict__ C,
                      int M, int N, int K) {
    __shared__ unsigned As[2][16][BPITCH];
    __shared__ unsigned Bs[2][16][BPITCH];

    int tid = threadIdx.x;
    int warp = tid >> 5, lane = tid & 31;
    int tig = lane & 3, gid = lane >> 2;
    int warpM = warp & 1, warpN = warp >> 1;
    int m0 = blockIdx.y * 128;
    int n0 = blockIdx.x * 128;

    float c[4][4][4];
    #pragma unroll
    for (int mf = 0; mf < 4; mf++)
        #pragma unroll
        for (int nf = 0; nf < 4; nf++)
            #pragma unroll
            for (int j = 0; j < 4; j++) c[mf][nf][j] = 0.f;

    float4 ra[2], rb[2];
    int arow[2], akq[2], brow[2], bnq[2];
    #pragma unroll
    for (int i = 0; i < 2; i++) {
        int li = tid + i*256;
        arow[i] = li >> 2;  akq[i] = (li & 3) * 4;
        brow[i] = li >> 5;  bnq[i] = (li & 31) * 4;
    }

    // prologue: load k-tile 0
    #pragma unroll
    for (int i = 0; i < 2; i++) {
        ra[i] = *(const float4*)&A[(size_t)(m0 + arow[i]) * K + akq[i]];
        rb[i] = *(const float4*)&B[(size_t)brow[i] * N + n0 + bnq[i]];
    }
    #pragma unroll
    for (int i = 0; i < 2; i++) {
        As[0][akq[i]+0][arow[i]] = f2tf(ra[i].x);
        As[0][akq[i]+1][arow[i]] = f2tf(ra[i].y);
        As[0][akq[i]+2][arow[i]] = f2tf(ra[i].z);
        As[0][akq[i]+3][arow[i]] = f2tf(ra[i].w);
        uint4 bu = make_uint4(f2tf(rb[i].x), f2tf(rb[i].y), f2tf(rb[i].z), f2tf(rb[i].w));
        *(uint4*)&Bs[0][brow[i]][bnq[i]] = bu;
    }
    __syncthreads();

    int nk = K / 16;
    for (int kt = 0; kt < nk; kt++) {
        int buf = kt & 1;
        if (kt + 1 < nk) {
            int k0 = (kt + 1) * 16;
            #pragma unroll
            for (int i = 0; i < 2; i++) {
                ra[i] = *(const float4*)&A[(size_t)(m0 + arow[i]) * K + k0 + akq[i]];
                rb[i] = *(const float4*)&B[(size_t)(k0 + brow[i]) * N + n0 + bnq[i]];
            }
        }
        // compute on buf
        #pragma unroll
        for (int kk = 0; kk < 16; kk += 8) {
            unsigned af[4][4];
            #pragma unroll
            for (int mf = 0; mf < 4; mf++) {
                int m = warpM*64 + mf*16 + gid;
                af[mf][0] = As[buf][kk+tig  ][m];
                af[mf][1] = As[buf][kk+tig  ][m+8];
                af[mf][2] = As[buf][kk+tig+4][m];
                af[mf][3] = As[buf][kk+tig+4][m+8];
            }
            unsigned bf[4][2];
            #pragma unroll
            for (int nf = 0; nf < 4; nf++) {
                int n = warpN*32 + nf*8 + gid;
                bf[nf][0] = Bs[buf][kk+tig  ][n];
                bf[nf][1] = Bs[buf][kk+tig+4][n];
            }
            #pragma unroll
            for (int mf = 0; mf < 4; mf++)
                #pragma unroll
                for (int nf = 0; nf < 4; nf++)
                    mma_tf32(c[mf][nf], af[mf][0], af[mf][1], af[mf][2], af[mf][3],
                             bf[nf][0], bf[nf][1]);
        }
        if (kt + 1 < nk) {
            int nb = (kt + 1) & 1;
            #pragma unroll
            for (int i = 0; i < 2; i++) {
                As[nb][akq[i]+0][arow[i]] = f2tf(ra[i].x);
                As[nb][akq[i]+1][arow[i]] = f2tf(ra[i].y);
                As[nb][akq[i]+2][arow[i]] = f2tf(ra[i].z);
                As[nb][akq[i]+3][arow[i]] = f2tf(ra[i].w);
                uint4 bu = make_uint4(f2tf(rb[i].x), f2tf(rb[i].y), f2tf(rb[i].z), f2tf(rb[i].w));
                *(uint4*)&Bs[nb][brow[i]][bnq[i]] = bu;
            }
        }
        __syncthreads();
    }

    // epilogue
    #pragma unroll
    for (int mf = 0; mf < 4; mf++) {
        int row = m0 + warpM*64 + mf*16 + gid;
        #pragma unroll
        for (int nf = 0; nf < 4; nf++) {
            int col = n0 + warpN*32 + nf*8 + 2*tig;
            float b0 = bias[col], b1 = bias[col+1];
            float2 w0 = make_float2(c[mf][nf][0] + b0, c[mf][nf][1] + b1);
            float2 w1 = make_float2(c[mf][nf][2] + b0, c[mf][nf][3] + b1);
            *(float2*)&C[(size_t)row * N + col]       = w0;
            *(float2*)&C[(size_t)(row+8) * N + col]   = w1;
        }
    }
}

// ---------------- flash attention, tf32 tensor cores ----------------------
// Block: one (b,h) x 64-query tile, 128 threads = 4 warps.
// Warp w owns rows 16w..16w+15 of the S tile -> softmax reduces only
// across the 4 tig lanes (shfl), no cross-warp reduction.
#define APITCH 72    // 64 + 8 pad
__global__ __launch_bounds__(128)
void attn_tf32_kernel(const float* __restrict__ qkv,
                      const int* __restrict__ mask,
                      float* __restrict__ out) {
    extern __shared__ unsigned smU[];
    unsigned* Qs = smU;                  // [64][72] tf32 bits
    unsigned* Ks = Qs + 64*APITCH;
    unsigned* Vs = Ks + 64*APITCH;
    unsigned* Ps = Vs + 64*APITCH;
    int* Ms = (int*)(Ps + 64*APITCH);    // [64]

    int bh = blockIdx.x;
    int b = bh >> 4, h = bh & 15;
    int q0 = blockIdx.y * 64;

    int tid = threadIdx.x;
    int warp = tid >> 5, lane = tid & 31;
    int tig = lane & 3, gid = lane >> 2;
    int qb = warp * 16;
    int row0 = qb + gid, row1 = qb + gid + 8;

    const size_t rs = QKV_N;
    const float* qbase = qkv + (size_t)(b*SEQ)*rs + h*HDIM;
    const float* kbase = qbase + EMB;
    const float* vbase = qbase + 2*EMB;
    const int*   mrow  = mask + b*SEQ;

    // load Q tile (tf32 bits)
    #pragma unroll
    for (int i = 0; i < 8; i++) {
        int li = tid + i*128;
        int r = li >> 4, dq = (li & 15) * 4;
        float4 v = *(const float4*)&qbase[(size_t)(q0 + r)*rs + dq];
        uint4 u = make_uint4(f2tf(v.x), f2tf(v.y), f2tf(v.z), f2tf(v.w));
        *(uint4*)&Qs[r*APITCH + dq] = u;
    }

    float o[8][4];
    #pragma unroll
    for (int nf = 0; nf < 8; nf++)
        #pragma unroll
        for (int j = 0; j < 4; j++) o[nf][j] = 0.f;
    float m0r = -1e30f, m1r = -1e30f, l0 = 0.f, l1 = 0.f;

    for (int k0 = 0; k0 < SEQ; k0 += 64) {
        __syncthreads();  // prev iteration's Ks/Vs reads done
        #pragma unroll
        for (int i = 0; i < 8; i++) {
            int li = tid + i*128;
            int r = li >> 4, dq = (li & 15) * 4;
            float4 kv = *(const float4*)&kbase[(size_t)(k0 + r)*rs + dq];
            float4 vv = *(const float4*)&vbase[(size_t)(k0 + r)*rs + dq];
            *(uint4*)&Ks[r*APITCH + dq] = make_uint4(f2tf(kv.x), f2tf(kv.y), f2tf(kv.z), f2tf(kv.w));
            *(uint4*)&Vs[r*APITCH + dq] = make_uint4(f2tf(vv.x), f2tf(vv.y), f2tf(vv.z), f2tf(vv.w));
        }
        if (tid < 64) Ms[tid] = mrow[k0 + tid];
        __syncthreads();

        // S = Q K^T
        float s[8][4];
        #pragma unroll
        for (int nf = 0; nf < 8; nf++)
            #pragma unroll
            for (int j = 0; j < 4; j++) s[nf][j] = 0.f;
        #pragma unroll
        for (int kk = 0; kk < 64; kk += 8) {
            unsigned a0 = Qs[row0*APITCH + kk + tig];
            unsigned a1 = Qs[row1*APITCH + kk + tig];
            unsigned a2 = Qs[row0*APITCH + kk + tig + 4];
            unsigned a3 = Qs[row1*APITCH + kk + tig + 4];
            #pragma unroll
            for (int nf = 0; nf < 8; nf++) {
                unsigned b0 = Ks[(nf*8 + gid)*APITCH + kk + tig];
                unsigned b1 = Ks[(nf*8 + gid)*APITCH + kk + tig + 4];
                mma_tf32(s[nf], a0, a1, a2, a3, b0, b1);
            }
        }

        // scale + mask
        #pragma unroll
        for (int nf = 0; nf < 8; nf++) {
            int col = nf*8 + 2*tig;
            int mv0 = Ms[col], mv1 = Ms[col+1];
            s[nf][0] = mv0 ? s[nf][0]*0.125f : -1e30f;
            s[nf][1] = mv1 ? s[nf][1]*0.125f : -1e30f;
            s[nf][2] = mv0 ? s[nf][2]*0.125f : -1e30f;
            s[nf][3] = mv1 ? s[nf][3]*0.125f : -1e30f;
        }

        // row max (rows row0, row1) across 8 frags + tig lanes
        float rm0 = -1e30f, rm1 = -1e30f;
        #pragma unroll
        for (int nf = 0; nf < 8; nf++) {
            rm0 = fmaxf(rm0, fmaxf(s[nf][0], s[nf][1]));
            rm1 = fmaxf(rm1, fmaxf(s[nf][2], s[nf][3]));
        }
        rm0 = fmaxf(rm0, __shfl_xor_sync(0xffffffffu, rm0, 1));
        rm0 = fmaxf(rm0, __shfl_xor_sync(0xffffffffu, rm0, 2));
        rm1 = fmaxf(rm1, __shfl_xor_sync(0xffffffffu, rm1, 1));
        rm1 = fmaxf(rm1, __shfl_xor_sync(0xffffffffu, rm1, 2));

        float mn0 = fmaxf(m0r, rm0), mn1 = fmaxf(m1r, rm1);
        float sc0 = __expf(m0r - mn0), sc1 = __expf(m1r - mn1);
        m0r = mn0; m1r = mn1;

        float rs0 = 0.f, rs1 = 0.f;
        #pragma unroll
        for (int nf = 0; nf < 8; nf++) {
            s[nf][0] = __expf(s[nf][0] - mn0);
            s[nf][1] = __expf(s[nf][1] - mn0);
            s[nf][2] = __expf(s[nf][2] - mn1);
            s[nf][3] = __expf(s[nf][3] - mn1);
            rs0 += s[nf][0] + s[nf][1];
            rs1 += s[nf][2] + s[nf][3];
        }
        rs0 += __shfl_xor_sync(0xffffffffu, rs0, 1);
        rs0 += __shfl_xor_sync(0xffffffffu, rs0, 2);
        rs1 += __shfl_xor_sync(0xffffffffu, rs1, 1);
        rs1 += __shfl_xor_sync(0xffffffffu, rs1, 2);
        l0 = l0*sc0 + rs0;
        l1 = l1*sc1 + rs1;

        #pragma unroll
        for (int nf = 0; nf < 8; nf++) {
            o[nf][0] *= sc0; o[nf][1] *= sc0;
            o[nf][2] *= sc1; o[nf][3] *= sc1;
        }

        // stage P (warp-private rows) as tf32
        __syncwarp();
        #pragma unroll
        for (int nf = 0; nf < 8; nf++) {
            int col = nf*8 + 2*tig;
            *(uint2*)&Ps[row0*APITCH + col] = make_uint2(f2tf(s[nf][0]), f2tf(s[nf][1]));
            *(uint2*)&Ps[row1*APITCH + col] = make_uint2(f2tf(s[nf][2]), f2tf(s[nf][3]));
        }
        __syncwarp();

        // O += P @ V
        #pragma unroll
        for (int kk = 0; kk < 64; kk += 8) {
            unsigned a0 = Ps[row0*APITCH + kk + tig];
            unsigned a1 = Ps[row1*APITCH + kk + tig];
            unsigned a2 = Ps[row0*APITCH + kk + tig + 4];
            unsigned a3 = Ps[row1*APITCH + kk + tig + 4];
            #pragma unroll
            for (int nf = 0; nf < 8; nf++) {
                unsigned b0 = Vs[(kk + tig)*APITCH + nf*8 + gid];
                unsigned b1 = Vs[(kk + tig + 4)*APITCH + nf*8 + gid];
                mma_tf32(o[nf], a0, a1, a2, a3, b0, b1);
            }
        }
    }

    // epilogue
    float inv0 = 1.f / l0, inv1 = 1.f / l1;
    #pragma unroll
    for (int nf = 0; nf < 8; nf++) {
        int col = nf*8 + 2*tig;
        size_t orow0 = (size_t)(b*SEQ + q0 + row0) * EMB + h*HDIM + col;
        size_t orow1 = (size_t)(b*SEQ + q0 + row1) * EMB + h*HDIM + col;
        *(float2*)&out[orow0] = make_float2(o[nf][0]*inv0, o[nf][1]*inv0);
        *(float2*)&out[orow1] = make_float2(o[nf][2]*inv1, o[nf][3]*inv1);
    }
}

// ---------------- launch ---------------------------------------------------
extern "C" void kernel_launch(void* const* d_in, const int* in_sizes, int n_in,
                              void* d_out, int out_size) {
    const float* x      = (const float*)d_in[0];
    const int*   mask   = (const int*)  d_in[1];
    const float* Wqkv   = (const float*)d_in[2];
    const float* bqkv   = (const float*)d_in[3];
    const float* Wout   = (const float*)d_in[4];
    const float* bout   = (const float*)d_in[5];
    const float* diag   = (const float*)d_in[6];
    const float* alpha  = (const float*)d_in[7];
    const float* bias_h = (const float*)d_in[8];
    float* out = (float*)d_out;

    float* qkv;  cudaGetSymbolAddress((void**)&qkv,  g_qkv);
    float* attn; cudaGetSymbolAddress((void**)&attn, g_attn);
    float* Wf;   cudaGetSymbolAddress((void**)&Wf,   g_Wf);
    float* bf;   cudaGetSymbolAddress((void**)&bf,   g_bf);

    build_T_kernel<<<64, 64>>>(diag, alpha);
    {
        dim3 grid((QKV_N + 255)/256, EMB);
        fold_w_kernel<<<grid, 256>>>(Wqkv);
        fold_b_kernel<<<(QKV_N + 255)/256, 256>>>(bqkv, bias_h);
    }
    {   // QKV GEMM: [4096,1024] @ [1024,3072]
        dim3 grid(QKV_N/128, M_ROWS/128);
        gemm_tf32_kernel<<<grid, 256>>>(x, Wf, bf, qkv, M_ROWS, QKV_N, EMB);
    }
    {   // attention
        size_t smem = (size_t)4 * 64 * APITCH * sizeof(unsigned) + 64*sizeof(int);
        cudaFuncSetAttribute(attn_tf32_kernel,
                             cudaFuncAttributeMaxDynamicSharedMemorySize, (int)smem);
        dim3 grid(BATCH*NHEAD, SEQ/64);
        attn_tf32_kernel<<<grid, 128, smem>>>(qkv, mask, attn);
    }
    {   // output projection: [4096,1024] @ [1024,1024]
        dim3 grid(EMB/128, M_ROWS/128);
        gemm_tf32_kernel<<<grid, 256>>>(attn, Wout, bout, out, M_ROWS, EMB, EMB);
    }
}

// round 4
// speedup vs baseline: 3.7192x; 1.0196x over previous
#include <cuda_runtime.h>
#include <cuda_bf16.h>
#include <cstdint>
#include <math.h>

#define BATCH 2
#define SEQ   2048
#define EMB   1024
#define NHEAD 16
#define HDIM  64
#define M_ROWS (BATCH*SEQ)      // 4096
#define QKV_N  (3*EMB)          // 3072

// ---------------- scratch (device globals, no allocation) ----------------
__device__ float g_T[HDIM*HDIM];
__device__ float g_Wf[EMB*QKV_N];
__device__ float g_bf[QKV_N];
__device__ float g_qkv[(size_t)M_ROWS*QKV_N];
__device__ float g_attn[(size_t)M_ROWS*EMB];

__device__ __forceinline__ unsigned f2tf(float f) {
    unsigned u;
    asm("cvt.rna.tf32.f32 %0, %1;" : "=r"(u) : "f"(f));
    return u;
}

__device__ __forceinline__ void mma_tf32(float c[4],
                                         unsigned a0, unsigned a1, unsigned a2, unsigned a3,
                                         unsigned b0, unsigned b1) {
    asm volatile(
        "mma.sync.aligned.m16n8k8.row.col.f32.tf32.tf32.f32 "
        "{%0,%1,%2,%3}, {%4,%5,%6,%7}, {%8,%9}, {%0,%1,%2,%3};"
        : "+f"(c[0]), "+f"(c[1]), "+f"(c[2]), "+f"(c[3])
        : "r"(a0), "r"(a1), "r"(a2), "r"(a3), "r"(b0), "r"(b1));
}

// ---------------- build T = I + (alpha/64) * H diag H --------------------
__global__ void build_T_kernel(const float* __restrict__ diag,
                               const float* __restrict__ alpha_p) {
    int i = blockIdx.x, j = threadIdx.x;
    float a = alpha_p[0] * (1.0f / 64.0f);
    int ij = i ^ j;
    float acc = 0.f;
    #pragma unroll
    for (int k = 0; k < 64; k++)
        acc += diag[k] * ((__popc(ij & k) & 1) ? -1.f : 1.f);
    g_T[i*64 + j] = a * acc + ((i == j) ? 1.f : 0.f);
}

// ---------------- fold T into QKV weights --------------------------------
__global__ void fold_w_kernel(const float* __restrict__ W) {
    int c = blockIdx.x * blockDim.x + threadIdx.x;
    int e = blockIdx.y;
    if (c >= QKV_N) return;
    size_t row = (size_t)e * QKV_N;
    if (c < 2*EMB) {
        int j = c & 63;
        int base = c - j;
        float acc = 0.f;
        #pragma unroll 8
        for (int d = 0; d < 64; d++)
            acc += W[row + base + d] * g_T[d*64 + j];
        g_Wf[row + c] = acc;
    } else {
        g_Wf[row + c] = W[row + c];
    }
}

__global__ void fold_b_kernel(const float* __restrict__ bqkv,
                              const float* __restrict__ bias_h) {
    int c = blockIdx.x * blockDim.x + threadIdx.x;
    if (c >= QKV_N) return;
    if (c < 2*EMB) {
        int j = c & 63;
        int base = c - j;
        float acc = bias_h[j];
        #pragma unroll 8
        for (int d = 0; d < 64; d++)
            acc += bqkv[base + d] * g_T[d*64 + j];
        g_bf[c] = acc;
    } else {
        g_bf[c] = bqkv[c];
    }
}

// ---------------- tf32 tensor-core GEMM: C = A@B + bias ------------------
// 128x256 block tile, 256 threads = 8 warps (2 along M x 4 along N),
// warp tile 64x64, m16n8k8 fragments, BK=16, double-buffered dynamic smem.
#define APCH 136   // 128 + 8
#define BPCH 264   // 256 + 8
#define A_SZ (16*APCH)   // words per stage
#define B_SZ (16*BPCH)
#define GEMM_SMEM ((2*A_SZ + 2*B_SZ) * 4)
__global__ __launch_bounds__(256, 1)
void gemm_tf32_kernel(const float* __restrict__ A,
                      const float* __restrict__ B,
                      const float* __restrict__ bias,
                      float* __restrict__ C,
                      int M, int N, int K) {
    extern __shared__ unsigned sh[];
    unsigned* As = sh;               // [2][16][APCH], layout [k][m]
    unsigned* Bs = sh + 2*A_SZ;      // [2][16][BPCH], layout [k][n]

    int tid = threadIdx.x;
    int warp = tid >> 5, lane = tid & 31;
    int tig = lane & 3, gid = lane >> 2;
    int warpM = warp & 1, warpN = warp >> 1;
    int m0 = blockIdx.y * 128;
    int n0 = blockIdx.x * 256;

    float c[4][8][4];
    #pragma unroll
    for (int mf = 0; mf < 4; mf++)
        #pragma unroll
        for (int nf = 0; nf < 8; nf++)
            #pragma unroll
            for (int j = 0; j < 4; j++) c[mf][nf][j] = 0.f;

    // load indices
    int arow[2], akq[2];
    #pragma unroll
    for (int i = 0; i < 2; i++) {
        int li = tid + i*256;
        arow[i] = li >> 2;  akq[i] = (li & 3) * 4;   // 128 rows x 4 quads
    }
    int brow[4], bnq[4];
    #pragma unroll
    for (int i = 0; i < 4; i++) {
        int li = tid + i*256;
        brow[i] = li >> 6;  bnq[i] = (li & 63) * 4;  // 16 rows x 64 quads
    }

    float4 ra[2], rb[4];
    // prologue: k-tile 0
    #pragma unroll
    for (int i = 0; i < 2; i++)
        ra[i] = *(const float4*)&A[(size_t)(m0 + arow[i]) * K + akq[i]];
    #pragma unroll
    for (int i = 0; i < 4; i++)
        rb[i] = *(const float4*)&B[(size_t)brow[i] * N + n0 + bnq[i]];
    #pragma unroll
    for (int i = 0; i < 2; i++) {
        unsigned* a0 = As + akq[i]*APCH + arow[i];
        a0[0*APCH] = f2tf(ra[i].x);
        a0[1*APCH] = f2tf(ra[i].y);
        a0[2*APCH] = f2tf(ra[i].z);
        a0[3*APCH] = f2tf(ra[i].w);
    }
    #pragma unroll
    for (int i = 0; i < 4; i++) {
        uint4 bu = make_uint4(f2tf(rb[i].x), f2tf(rb[i].y), f2tf(rb[i].z), f2tf(rb[i].w));
        *(uint4*)&Bs[brow[i]*BPCH + bnq[i]] = bu;
    }
    __syncthreads();

    int nk = K / 16;
    for (int kt = 0; kt < nk; kt++) {
        unsigned* Ab = As + (kt & 1) * A_SZ;
        unsigned* Bb = Bs + (kt & 1) * B_SZ;
        if (kt + 1 < nk) {
            int k0 = (kt + 1) * 16;
            #pragma unroll
            for (int i = 0; i < 2; i++)
                ra[i] = *(const float4*)&A[(size_t)(m0 + arow[i]) * K + k0 + akq[i]];
            #pragma unroll
            for (int i = 0; i < 4; i++)
                rb[i] = *(const float4*)&B[(size_t)(k0 + brow[i]) * N + n0 + bnq[i]];
        }
        #pragma unroll
        for (int kk = 0; kk < 16; kk += 8) {
            unsigned af[4][4];
            #pragma unroll
            for (int mf = 0; mf < 4; mf++) {
                int m = warpM*64 + mf*16 + gid;
                af[mf][0] = Ab[(kk+tig  )*APCH + m];
                af[mf][1] = Ab[(kk+tig  )*APCH + m + 8];
                af[mf][2] = Ab[(kk+tig+4)*APCH + m];
                af[mf][3] = Ab[(kk+tig+4)*APCH + m + 8];
            }
            unsigned bf[8][2];
            #pragma unroll
            for (int nf = 0; nf < 8; nf++) {
                int n = warpN*64 + nf*8 + gid;
                bf[nf][0] = Bb[(kk+tig  )*BPCH + n];
                bf[nf][1] = Bb[(kk+tig+4)*BPCH + n];
            }
            #pragma unroll
            for (int mf = 0; mf < 4; mf++)
                #pragma unroll
                for (int nf = 0; nf < 8; nf++)
                    mma_tf32(c[mf][nf], af[mf][0], af[mf][1], af[mf][2], af[mf][3],
                             bf[nf][0], bf[nf][1]);
        }
        if (kt + 1 < nk) {
            unsigned* An = As + ((kt + 1) & 1) * A_SZ;
            unsigned* Bn = Bs + ((kt + 1) & 1) * B_SZ;
            #pragma unroll
            for (int i = 0; i < 2; i++) {
                unsigned* a0 = An + akq[i]*APCH + arow[i];
                a0[0*APCH] = f2tf(ra[i].x);
                a0[1*APCH] = f2tf(ra[i].y);
                a0[2*APCH] = f2tf(ra[i].z);
                a0[3*APCH] = f2tf(ra[i].w);
            }
            #pragma unroll
            for (int i = 0; i < 4; i++) {
                uint4 bu = make_uint4(f2tf(rb[i].x), f2tf(rb[i].y), f2tf(rb[i].z), f2tf(rb[i].w));
                *(uint4*)&Bn[brow[i]*BPCH + bnq[i]] = bu;
            }
        }
        __syncthreads();
    }

    // epilogue
    #pragma unroll
    for (int mf = 0; mf < 4; mf++) {
        int row = m0 + warpM*64 + mf*16 + gid;
        #pragma unroll
        for (int nf = 0; nf < 8; nf++) {
            int col = n0 + warpN*64 + nf*8 + 2*tig;
            float b0 = bias[col], b1 = bias[col+1];
            *(float2*)&C[(size_t)row * N + col]     = make_float2(c[mf][nf][0] + b0, c[mf][nf][1] + b1);
            *(float2*)&C[(size_t)(row+8) * N + col] = make_float2(c[mf][nf][2] + b0, c[mf][nf][3] + b1);
        }
    }
}

// ---------------- flash attention, tf32 mma.sync, Bq=128 ------------------
// Block: one (b,h) x 128-query tile, 256 threads = 8 warps.
// Warp w owns S rows 16w..16w+15 -> softmax reduces across tig lanes only.
#define APITCH 72
#define ATTN_SMEM (((128+64+64+128)*APITCH)*4 + 64*4)
__global__ __launch_bounds__(256)
void attn_tf32_kernel(const float* __restrict__ qkv,
                      const int* __restrict__ mask,
                      float* __restrict__ out) {
    extern __shared__ unsigned smU[];
    unsigned* Qs = smU;                   // [128][72]
    unsigned* Ks = Qs + 128*APITCH;       // [64][72]
    unsigned* Vs = Ks + 64*APITCH;        // [64][72]
    unsigned* Ps = Vs + 64*APITCH;        // [128][72]
    int* Ms = (int*)(Ps + 128*APITCH);    // [64]

    int bh = blockIdx.x;
    int b = bh >> 4, h = bh & 15;
    int q0 = blockIdx.y * 128;

    int tid = threadIdx.x;
    int warp = tid >> 5, lane = tid & 31;
    int tig = lane & 3, gid = lane >> 2;
    int row0 = warp*16 + gid, row1 = row0 + 8;

    const size_t rs = QKV_N;
    const float* qbase = qkv + (size_t)(b*SEQ)*rs + h*HDIM;
    const float* kbase = qbase + EMB;
    const float* vbase = qbase + 2*EMB;
    const int*   mrow  = mask + b*SEQ;

    // load Q tile (128 x 64)
    #pragma unroll
    for (int i = 0; i < 8; i++) {
        int li = tid + i*256;
        int r = li >> 4, dq = (li & 15) * 4;
        float4 v = *(const float4*)&qbase[(size_t)(q0 + r)*rs + dq];
        *(uint4*)&Qs[r*APITCH + dq] = make_uint4(f2tf(v.x), f2tf(v.y), f2tf(v.z), f2tf(v.w));
    }

    float o[8][4];
    #pragma unroll
    for (int nf = 0; nf < 8; nf++)
        #pragma unroll
        for (int j = 0; j < 4; j++) o[nf][j] = 0.f;
    float m0r = -1e30f, m1r = -1e30f, l0 = 0.f, l1 = 0.f;

    for (int k0 = 0; k0 < SEQ; k0 += 64) {
        __syncthreads();
        #pragma unroll
        for (int i = 0; i < 4; i++) {
            int li = tid + i*256;
            int r = li >> 4, dq = (li & 15) * 4;
            float4 kv = *(const float4*)&kbase[(size_t)(k0 + r)*rs + dq];
            float4 vv = *(const float4*)&vbase[(size_t)(k0 + r)*rs + dq];
            *(uint4*)&Ks[r*APITCH + dq] = make_uint4(f2tf(kv.x), f2tf(kv.y), f2tf(kv.z), f2tf(kv.w));
            *(uint4*)&Vs[r*APITCH + dq] = make_uint4(f2tf(vv.x), f2tf(vv.y), f2tf(vv.z), f2tf(vv.w));
        }
        if (tid < 64) Ms[tid] = mrow[k0 + tid];
        __syncthreads();

        // S = Q K^T (16 rows x 64 keys per warp)
        float s[8][4];
        #pragma unroll
        for (int nf = 0; nf < 8; nf++)
            #pragma unroll
            for (int j = 0; j < 4; j++) s[nf][j] = 0.f;
        #pragma unroll
        for (int kk = 0; kk < 64; kk += 8) {
            unsigned a0 = Qs[row0*APITCH + kk + tig];
            unsigned a1 = Qs[row1*APITCH + kk + tig];
            unsigned a2 = Qs[row0*APITCH + kk + tig + 4];
            unsigned a3 = Qs[row1*APITCH + kk + tig + 4];
            #pragma unroll
            for (int nf = 0; nf < 8; nf++) {
                unsigned b0 = Ks[(nf*8 + gid)*APITCH + kk + tig];
                unsigned b1 = Ks[(nf*8 + gid)*APITCH + kk + tig + 4];
                mma_tf32(s[nf], a0, a1, a2, a3, b0, b1);
            }
        }

        #pragma unroll
        for (int nf = 0; nf < 8; nf++) {
            int col = nf*8 + 2*tig;
            int mv0 = Ms[col], mv1 = Ms[col+1];
            s[nf][0] = mv0 ? s[nf][0]*0.125f : -1e30f;
            s[nf][1] = mv1 ? s[nf][1]*0.125f : -1e30f;
            s[nf][2] = mv0 ? s[nf][2]*0.125f : -1e30f;
            s[nf][3] = mv1 ? s[nf][3]*0.125f : -1e30f;
        }

        float rm0 = -1e30f, rm1 = -1e30f;
        #pragma unroll
        for (int nf = 0; nf < 8; nf++) {
            rm0 = fmaxf(rm0, fmaxf(s[nf][0], s[nf][1]));
            rm1 = fmaxf(rm1, fmaxf(s[nf][2], s[nf][3]));
        }
        rm0 = fmaxf(rm0, __shfl_xor_sync(0xffffffffu, rm0, 1));
        rm0 = fmaxf(rm0, __shfl_xor_sync(0xffffffffu, rm0, 2));
        rm1 = fmaxf(rm1, __shfl_xor_sync(0xffffffffu, rm1, 1));
        rm1 = fmaxf(rm1, __shfl_xor_sync(0xffffffffu, rm1, 2));

        float mn0 = fmaxf(m0r, rm0), mn1 = fmaxf(m1r, rm1);
        float sc0 = __expf(m0r - mn0), sc1 = __expf(m1r - mn1);
        m0r = mn0; m1r = mn1;

        float rs0 = 0.f, rs1 = 0.f;
        #pragma unroll
        for (int nf = 0; nf < 8; nf++) {
            s[nf][0] = __expf(s[nf][0] - mn0);
            s[nf][1] = __expf(s[nf][1] - mn0);
            s[nf][2] = __expf(s[nf][2] - mn1);
            s[nf][3] = __expf(s[nf][3] - mn1);
            rs0 += s[nf][0] + s[nf][1];
            rs1 += s[nf][2] + s[nf][3];
        }
        rs0 += __shfl_xor_sync(0xffffffffu, rs0, 1);
        rs0 += __shfl_xor_sync(0xffffffffu, rs0, 2);
        rs1 += __shfl_xor_sync(0xffffffffu, rs1, 1);
        rs1 += __shfl_xor_sync(0xffffffffu, rs1, 2);
        l0 = l0*sc0 + rs0;
        l1 = l1*sc1 + rs1;

        #pragma unroll
        for (int nf = 0; nf < 8; nf++) {
            o[nf][0] *= sc0; o[nf][1] *= sc0;
            o[nf][2] *= sc1; o[nf][3] *= sc1;
        }

        // stage P (warp-private rows)
        __syncwarp();
        #pragma unroll
        for (int nf = 0; nf < 8; nf++) {
            int col = nf*8 + 2*tig;
            *(uint2*)&Ps[row0*APITCH + col] = make_uint2(f2tf(s[nf][0]), f2tf(s[nf][1]));
            *(uint2*)&Ps[row1*APITCH + col] = make_uint2(f2tf(s[nf][2]), f2tf(s[nf][3]));
        }
        __syncwarp();

        // O += P @ V
        #pragma unroll
        for (int kk = 0; kk < 64; kk += 8) {
            unsigned a0 = Ps[row0*APITCH + kk + tig];
            unsigned a1 = Ps[row1*APITCH + kk + tig];
            unsigned a2 = Ps[row0*APITCH + kk + tig + 4];
            unsigned a3 = Ps[row1*APITCH + kk + tig + 4];
            #pragma unroll
            for (int nf = 0; nf < 8; nf++) {
                unsigned b0 = Vs[(kk + tig)*APITCH + nf*8 + gid];
                unsigned b1 = Vs[(kk + tig + 4)*APITCH + nf*8 + gid];
                mma_tf32(o[nf], a0, a1, a2, a3, b0, b1);
            }
        }
    }

    // epilogue
    float inv0 = 1.f / l0, inv1 = 1.f / l1;
    #pragma unroll
    for (int nf = 0; nf < 8; nf++) {
        int col = nf*8 + 2*tig;
        size_t orow0 = (size_t)(b*SEQ + q0 + row0) * EMB + h*HDIM + col;
        size_t orow1 = (size_t)(b*SEQ + q0 + row1) * EMB + h*HDIM + col;
        *(float2*)&out[orow0] = make_float2(o[nf][0]*inv0, o[nf][1]*inv0);
        *(float2*)&out[orow1] = make_float2(o[nf][2]*inv1, o[nf][3]*inv1);
    }
}

// ---------------- launch ---------------------------------------------------
extern "C" void kernel_launch(void* const* d_in, const int* in_sizes, int n_in,
                              void* d_out, int out_size) {
    const float* x      = (const float*)d_in[0];
    const int*   mask   = (const int*)  d_in[1];
    const float* Wqkv   = (const float*)d_in[2];
    const float* bqkv   = (const float*)d_in[3];
    const float* Wout   = (const float*)d_in[4];
    const float* bout   = (const float*)d_in[5];
    const float* diag   = (const float*)d_in[6];
    const float* alpha  = (const float*)d_in[7];
    const float* bias_h = (const float*)d_in[8];
    float* out = (float*)d_out;

    float* qkv;  cudaGetSymbolAddress((void**)&qkv,  g_qkv);
    float* attn; cudaGetSymbolAddress((void**)&attn, g_attn);
    float* Wf;   cudaGetSymbolAddress((void**)&Wf,   g_Wf);
    float* bf;   cudaGetSymbolAddress((void**)&bf,   g_bf);

    build_T_kernel<<<64, 64>>>(diag, alpha);
    {
        dim3 grid((QKV_N + 255)/256, EMB);
        fold_w_kernel<<<grid, 256>>>(Wqkv);
        fold_b_kernel<<<(QKV_N + 255)/256, 256>>>(bqkv, bias_h);
    }

    cudaFuncSetAttribute(gemm_tf32_kernel,
                         cudaFuncAttributeMaxDynamicSharedMemorySize, GEMM_SMEM);
    {   // QKV GEMM: [4096,1024] @ [1024,3072]
        dim3 grid(QKV_N/256, M_ROWS/128);
        gemm_tf32_kernel<<<grid, 256, GEMM_SMEM>>>(x, Wf, bf, qkv, M_ROWS, QKV_N, EMB);
    }
    {   // attention
        cudaFuncSetAttribute(attn_tf32_kernel,
                             cudaFuncAttributeMaxDynamicSharedMemorySize, ATTN_SMEM);
        dim3 grid(BATCH*NHEAD, SEQ/128);
        attn_tf32_kernel<<<grid, 256, ATTN_SMEM>>>(qkv, mask, attn);
    }
    {   // output projection: [4096,1024] @ [1024,1024]
        dim3 grid(EMB/256, M_ROWS/128);
        gemm_tf32_kernel<<<grid, 256, GEMM_SMEM>>>(attn, Wout, bout, out, M_ROWS, EMB, EMB);
    }
}

// round 5
// speedup vs baseline: 4.1296x; 1.1103x over previous
#include <cuda_runtime.h>
#include <cuda_bf16.h>
#include <cstdint>
#include <math.h>

#define BATCH 2
#define SEQ   2048
#define EMB   1024
#define NHEAD 16
#define HDIM  64
#define M_ROWS (BATCH*SEQ)      // 4096
#define QKV_N  (3*EMB)          // 3072

// ---------------- scratch (device globals, no allocation) ----------------
__device__ float g_T[HDIM*HDIM];
__device__ float g_Wf[EMB*QKV_N];                // folded + RNA-tf32
__device__ float g_WoR[(size_t)EMB*EMB];         // RNA(Wout)
__device__ float g_bf[QKV_N];
__device__ float g_xr[(size_t)M_ROWS*EMB];       // RNA(x)
__device__ float g_qkv[(size_t)M_ROWS*QKV_N];    // RNA'd by GEMM epilogue
__device__ float g_attn[(size_t)M_ROWS*EMB];     // RNA'd by attn epilogue

__device__ __forceinline__ unsigned f2tf(float f) {
    unsigned u;
    asm("cvt.rna.tf32.f32 %0, %1;" : "=r"(u) : "f"(f));
    return u;
}
__device__ __forceinline__ float rnaf(float f) { return __uint_as_float(f2tf(f)); }

__device__ __forceinline__ uint32_t smem_u32(const void* p) {
    uint32_t a;
    asm("{ .reg .u64 t; cvta.to.shared.u64 t, %1; cvt.u32.u64 %0, t; }"
        : "=r"(a) : "l"(p));
    return a;
}

__device__ __forceinline__ void cp16(uint32_t dst, const void* src) {
    asm volatile("cp.async.cg.shared.global [%0], [%1], 16;" :: "r"(dst), "l"(src));
}
#define CP_COMMIT() asm volatile("cp.async.commit_group;" ::: "memory")
#define CP_WAIT(n)  asm volatile("cp.async.wait_group %0;" :: "n"(n) : "memory")

__device__ __forceinline__ void mma_tf32(float c[4],
                                         unsigned a0, unsigned a1, unsigned a2, unsigned a3,
                                         unsigned b0, unsigned b1) {
    asm volatile(
        "mma.sync.aligned.m16n8k8.row.col.f32.tf32.tf32.f32 "
        "{%0,%1,%2,%3}, {%4,%5,%6,%7}, {%8,%9}, {%0,%1,%2,%3};"
        : "+f"(c[0]), "+f"(c[1]), "+f"(c[2]), "+f"(c[3])
        : "r"(a0), "r"(a1), "r"(a2), "r"(a3), "r"(b0), "r"(b1));
}

// ---------------- build T = I + (alpha/64) * H diag H --------------------
__global__ void build_T_kernel(const float* __restrict__ diag,
                               const float* __restrict__ alpha_p) {
    int i = blockIdx.x, j = threadIdx.x;
    float a = alpha_p[0] * (1.0f / 64.0f);
    int ij = i ^ j;
    float acc = 0.f;
    #pragma unroll
    for (int k = 0; k < 64; k++)
        acc += diag[k] * ((__popc(ij & k) & 1) ? -1.f : 1.f);
    g_T[i*64 + j] = a * acc + ((i == j) ? 1.f : 0.f);
}

// ---------------- fold T into QKV weights (emit RNA-tf32) ----------------
__global__ void fold_w_kernel(const float* __restrict__ W) {
    int c = blockIdx.x * blockDim.x + threadIdx.x;
    int e = blockIdx.y;
    if (c >= QKV_N) return;
    size_t row = (size_t)e * QKV_N;
    if (c < 2*EMB) {
        int j = c & 63;
        int base = c - j;
        float acc = 0.f;
        #pragma unroll 8
        for (int d = 0; d < 64; d++)
            acc += W[row + base + d] * g_T[d*64 + j];
        g_Wf[row + c] = rnaf(acc);
    } else {
        g_Wf[row + c] = rnaf(W[row + c]);
    }
}

__global__ void fold_b_kernel(const float* __restrict__ bqkv,
                              const float* __restrict__ bias_h) {
    int c = blockIdx.x * blockDim.x + threadIdx.x;
    if (c >= QKV_N) return;
    if (c < 2*EMB) {
        int j = c & 63;
        int base = c - j;
        float acc = bias_h[j];
        #pragma unroll 8
        for (int d = 0; d < 64; d++)
            acc += bqkv[base + d] * g_T[d*64 + j];
        g_bf[c] = acc;
    } else {
        g_bf[c] = bqkv[c];
    }
}

// ---------------- elementwise RNA-to-tf32 ---------------------------------
__global__ void rna_kernel(const float* __restrict__ in, float* __restrict__ out, int n4) {
    int i = blockIdx.x * blockDim.x + threadIdx.x;
    if (i >= n4) return;
    float4 v = ((const float4*)in)[i];
    v.x = rnaf(v.x); v.y = rnaf(v.y); v.z = rnaf(v.z); v.w = rnaf(v.w);
    ((float4*)out)[i] = v;
}

// ---------------- tf32 GEMM: C = A@B + bias, cp.async 3-stage -------------
// 128x256 tile, 256 threads = 8 warps (2M x 4N), warp 64x64.
// A staged [m][k] pitch 20 (bank=20g+t, conflict-free); B [k][n] pitch 264.
#define AP2 20
#define BP2 264
#define ASTG (128*AP2)
#define BSTG (16*BP2)
#define GSTG (ASTG + BSTG)
#define GEMM_SMEM (3*GSTG*4)
__global__ __launch_bounds__(256, 1)
void gemm_tf32_kernel(const float* __restrict__ A,
                      const float* __restrict__ B,
                      const float* __restrict__ bias,
                      float* __restrict__ C,
                      int M, int N, int K, int roundOut) {
    extern __shared__ unsigned sh[];
    uint32_t shA = smem_u32(sh);

    int tid = threadIdx.x;
    int warp = tid >> 5, lane = tid & 31;
    int tig = lane & 3, gid = lane >> 2;
    int warpM = warp & 1, warpN = warp >> 1;
    int m0 = blockIdx.y * 128;
    int n0 = blockIdx.x * 256;

    float c[4][8][4];
    #pragma unroll
    for (int mf = 0; mf < 4; mf++)
        #pragma unroll
        for (int nf = 0; nf < 8; nf++)
            #pragma unroll
            for (int j = 0; j < 4; j++) c[mf][nf][j] = 0.f;

    int nk = K / 16;

    auto issue = [&](int s, int k0) {
        uint32_t base = shA + (uint32_t)s * GSTG * 4;
        #pragma unroll
        for (int i = 0; i < 2; i++) {
            int li = tid + i*256;
            int row = li >> 2, kq = li & 3;
            cp16(base + (row*AP2 + kq*4)*4, A + (size_t)(m0 + row)*K + k0 + kq*4);
        }
        #pragma unroll
        for (int i = 0; i < 4; i++) {
            int li = tid + i*256;
            int kr = li >> 6, nq = li & 63;
            cp16(base + (ASTG + kr*BP2 + nq*4)*4, B + (size_t)(k0 + kr)*N + n0 + nq*4);
        }
        CP_COMMIT();
    };

    issue(0, 0);
    issue(1, 16);

    for (int kt = 0; kt < nk; kt++) {
        if (kt + 2 < nk) {
            issue((kt + 2) % 3, (kt + 2) * 16);
            CP_WAIT(2);
        } else if (kt + 1 < nk) {
            CP_WAIT(1);
        } else {
            CP_WAIT(0);
        }
        __syncthreads();

        unsigned* Ab = sh + (kt % 3) * GSTG;
        unsigned* Bb = Ab + ASTG;

        #pragma unroll
        for (int kk = 0; kk < 16; kk += 8) {
            unsigned af[4][4];
            #pragma unroll
            for (int mf = 0; mf < 4; mf++) {
                int m = warpM*64 + mf*16 + gid;
                af[mf][0] = Ab[m*AP2 + kk + tig];
                af[mf][1] = Ab[(m+8)*AP2 + kk + tig];
                af[mf][2] = Ab[m*AP2 + kk + tig + 4];
                af[mf][3] = Ab[(m+8)*AP2 + kk + tig + 4];
            }
            unsigned bf[8][2];
            #pragma unroll
            for (int nf = 0; nf < 8; nf++) {
                int n = warpN*64 + nf*8 + gid;
                bf[nf][0] = Bb[(kk+tig  )*BP2 + n];
                bf[nf][1] = Bb[(kk+tig+4)*BP2 + n];
            }
            #pragma unroll
            for (int mf = 0; mf < 4; mf++)
                #pragma unroll
                for (int nf = 0; nf < 8; nf++)
                    mma_tf32(c[mf][nf], af[mf][0], af[mf][1], af[mf][2], af[mf][3],
                             bf[nf][0], bf[nf][1]);
        }
        __syncthreads();
    }

    // epilogue
    #pragma unroll
    for (int mf = 0; mf < 4; mf++) {
        int row = m0 + warpM*64 + mf*16 + gid;
        #pragma unroll
        for (int nf = 0; nf < 8; nf++) {
            int col = n0 + warpN*64 + nf*8 + 2*tig;
            float b0 = bias[col], b1 = bias[col+1];
            float v00 = c[mf][nf][0] + b0, v01 = c[mf][nf][1] + b1;
            float v10 = c[mf][nf][2] + b0, v11 = c[mf][nf][3] + b1;
            if (roundOut) { v00 = rnaf(v00); v01 = rnaf(v01); v10 = rnaf(v10); v11 = rnaf(v11); }
            *(float2*)&C[(size_t)row * N + col]     = make_float2(v00, v01);
            *(float2*)&C[(size_t)(row+8) * N + col] = make_float2(v10, v11);
        }
    }
}

// ---------------- flash attention, tf32, cp.async 2-stage K/V -------------
// Bq=128, 256 threads = 8 warps; warp owns S rows 16w..16w+15.
// Pitches: Q/K/P = 68 (==4 mod 32), V = 72 (==8 mod 32): conflict-free frags.
#define QP 68
#define VP 72
#define KSTG (64*QP)
#define VSTG (64*VP)
#define ATTN_SMEM ((128*QP + 128*QP + 2*KSTG + 2*VSTG)*4 + 2*64*4)
__global__ __launch_bounds__(256, 1)
void attn_tf32_kernel(const float* __restrict__ qkv,
                      const int* __restrict__ mask,
                      float* __restrict__ out) {
    extern __shared__ unsigned smU[];
    unsigned* Qs = smU;                     // [128][68]
    unsigned* Ps = Qs + 128*QP;             // [128][68]
    unsigned* Ks = Ps + 128*QP;             // [2][64][68]
    unsigned* Vs = Ks + 2*KSTG;             // [2][64][72]
    int*      Ms = (int*)(Vs + 2*VSTG);     // [2][64]

    uint32_t kA = smem_u32(Ks);
    uint32_t vA = smem_u32(Vs);
    uint32_t mA = smem_u32(Ms);

    int bh = blockIdx.x;
    int b = bh >> 4, h = bh & 15;
    int q0 = blockIdx.y * 128;

    int tid = threadIdx.x;
    int warp = tid >> 5, lane = tid & 31;
    int tig = lane & 3, gid = lane >> 2;
    int row0 = warp*16 + gid, row1 = row0 + 8;

    const size_t rs = QKV_N;
    const float* qbase = qkv + (size_t)(b*SEQ)*rs + h*HDIM;
    const float* kbase = qbase + EMB;
    const float* vbase = qbase + 2*EMB;
    const int*   mrow  = mask + b*SEQ;

    auto issue = [&](int s, int k0) {
        #pragma unroll
        for (int i = 0; i < 4; i++) {
            int li = tid + i*256;
            int r = li >> 4, dq = (li & 15) * 4;
            cp16(kA + (s*KSTG + r*QP + dq)*4, kbase + (size_t)(k0 + r)*rs + dq);
            cp16(vA + (s*VSTG + r*VP + dq)*4, vbase + (size_t)(k0 + r)*rs + dq);
        }
        if (tid < 16) cp16(mA + s*256 + tid*16, mrow + k0 + tid*4);
        CP_COMMIT();
    };

    // load Q tile (values already tf32-rounded)
    #pragma unroll
    for (int i = 0; i < 8; i++) {
        int li = tid + i*256;
        int r = li >> 4, dq = (li & 15) * 4;
        uint4 v = *(const uint4*)&qbase[(size_t)(q0 + r)*rs + dq];
        *(uint4*)&Qs[r*QP + dq] = v;
    }

    issue(0, 0);
    issue(1, 64);

    float o[8][4];
    #pragma unroll
    for (int nf = 0; nf < 8; nf++)
        #pragma unroll
        for (int j = 0; j < 4; j++) o[nf][j] = 0.f;
    float m0r = -1e30f, m1r = -1e30f, l0 = 0.f, l1 = 0.f;

    const int NT = SEQ / 64;
    for (int kt = 0; kt < NT; kt++) {
        int st = kt & 1;
        if (kt + 1 < NT) { CP_WAIT(1); } else { CP_WAIT(0); }
        __syncthreads();

        unsigned* Kb = Ks + st*KSTG;
        unsigned* Vb = Vs + st*VSTG;
        int*      Mb = Ms + st*64;

        // S = Q K^T
        float s[8][4];
        #pragma unroll
        for (int nf = 0; nf < 8; nf++)
            #pragma unroll
            for (int j = 0; j < 4; j++) s[nf][j] = 0.f;
        #pragma unroll
        for (int kk = 0; kk < 64; kk += 8) {
            unsigned a0 = Qs[row0*QP + kk + tig];
            unsigned a1 = Qs[row1*QP + kk + tig];
            unsigned a2 = Qs[row0*QP + kk + tig + 4];
            unsigned a3 = Qs[row1*QP + kk + tig + 4];
            #pragma unroll
            for (int nf = 0; nf < 8; nf++) {
                unsigned b0 = Kb[(nf*8 + gid)*QP + kk + tig];
                unsigned b1 = Kb[(nf*8 + gid)*QP + kk + tig + 4];
                mma_tf32(s[nf], a0, a1, a2, a3, b0, b1);
            }
        }

        #pragma unroll
        for (int nf = 0; nf < 8; nf++) {
            int col = nf*8 + 2*tig;
            int mv0 = Mb[col], mv1 = Mb[col+1];
            s[nf][0] = mv0 ? s[nf][0]*0.125f : -1e30f;
            s[nf][1] = mv1 ? s[nf][1]*0.125f : -1e30f;
            s[nf][2] = mv0 ? s[nf][2]*0.125f : -1e30f;
            s[nf][3] = mv1 ? s[nf][3]*0.125f : -1e30f;
        }

        float rm0 = -1e30f, rm1 = -1e30f;
        #pragma unroll
        for (int nf = 0; nf < 8; nf++) {
            rm0 = fmaxf(rm0, fmaxf(s[nf][0], s[nf][1]));
            rm1 = fmaxf(rm1, fmaxf(s[nf][2], s[nf][3]));
        }
        rm0 = fmaxf(rm0, __shfl_xor_sync(0xffffffffu, rm0, 1));
        rm0 = fmaxf(rm0, __shfl_xor_sync(0xffffffffu, rm0, 2));
        rm1 = fmaxf(rm1, __shfl_xor_sync(0xffffffffu, rm1, 1));
        rm1 = fmaxf(rm1, __shfl_xor_sync(0xffffffffu, rm1, 2));

        float mn0 = fmaxf(m0r, rm0), mn1 = fmaxf(m1r, rm1);
        float sc0 = __expf(m0r - mn0), sc1 = __expf(m1r - mn1);
        m0r = mn0; m1r = mn1;

        float rs0 = 0.f, rs1 = 0.f;
        #pragma unroll
        for (int nf = 0; nf < 8; nf++) {
            s[nf][0] = __expf(s[nf][0] - mn0);
            s[nf][1] = __expf(s[nf][1] - mn0);
            s[nf][2] = __expf(s[nf][2] - mn1);
            s[nf][3] = __expf(s[nf][3] - mn1);
            rs0 += s[nf][0] + s[nf][1];
            rs1 += s[nf][2] + s[nf][3];
        }
        rs0 += __shfl_xor_sync(0xffffffffu, rs0, 1);
        rs0 += __shfl_xor_sync(0xffffffffu, rs0, 2);
        rs1 += __shfl_xor_sync(0xffffffffu, rs1, 1);
        rs1 += __shfl_xor_sync(0xffffffffu, rs1, 2);
        l0 = l0*sc0 + rs0;
        l1 = l1*sc1 + rs1;

        #pragma unroll
        for (int nf = 0; nf < 8; nf++) {
            o[nf][0] *= sc0; o[nf][1] *= sc0;
            o[nf][2] *= sc1; o[nf][3] *= sc1;
        }

        // stage P (warp-private rows)
        __syncwarp();
        #pragma unroll
        for (int nf = 0; nf < 8; nf++) {
            int col = nf*8 + 2*tig;
            *(uint2*)&Ps[row0*QP + col] = make_uint2(f2tf(s[nf][0]), f2tf(s[nf][1]));
            *(uint2*)&Ps[row1*QP + col] = make_uint2(f2tf(s[nf][2]), f2tf(s[nf][3]));
        }
        __syncwarp();

        // O += P @ V
        #pragma unroll
        for (int kk = 0; kk < 64; kk += 8) {
            unsigned a0 = Ps[row0*QP + kk + tig];
            unsigned a1 = Ps[row1*QP + kk + tig];
            unsigned a2 = Ps[row0*QP + kk + tig + 4];
            unsigned a3 = Ps[row1*QP + kk + tig + 4];
            #pragma unroll
            for (int nf = 0; nf < 8; nf++) {
                unsigned b0 = Vb[(kk + tig)*VP + nf*8 + gid];
                unsigned b1 = Vb[(kk + tig + 4)*VP + nf*8 + gid];
                mma_tf32(o[nf], a0, a1, a2, a3, b0, b1);
            }
        }
        __syncthreads();
        if (kt + 2 < NT) issue(st, (kt + 2) * 64);
    }

    // epilogue: normalize + RNA (consumed by out-proj GEMM)
    float inv0 = 1.f / l0, inv1 = 1.f / l1;
    #pragma unroll
    for (int nf = 0; nf < 8; nf++) {
        int col = nf*8 + 2*tig;
        size_t orow0 = (size_t)(b*SEQ + q0 + row0) * EMB + h*HDIM + col;
        size_t orow1 = (size_t)(b*SEQ + q0 + row1) * EMB + h*HDIM + col;
        *(float2*)&out[orow0] = make_float2(rnaf(o[nf][0]*inv0), rnaf(o[nf][1]*inv0));
        *(float2*)&out[orow1] = make_float2(rnaf(o[nf][2]*inv1), rnaf(o[nf][3]*inv1));
    }
}

// ---------------- launch ---------------------------------------------------
extern "C" void kernel_launch(void* const* d_in, const int* in_sizes, int n_in,
                              void* d_out, int out_size) {
    const float* x      = (const float*)d_in[0];
    const int*   mask   = (const int*)  d_in[1];
    const float* Wqkv   = (const float*)d_in[2];
    const float* bqkv   = (const float*)d_in[3];
    const float* Wout   = (const float*)d_in[4];
    const float* bout   = (const float*)d_in[5];
    const float* diag   = (const float*)d_in[6];
    const float* alpha  = (const float*)d_in[7];
    const float* bias_h = (const float*)d_in[8];
    float* out = (float*)d_out;

    float* qkv;  cudaGetSymbolAddress((void**)&qkv,  g_qkv);
    float* attn; cudaGetSymbolAddress((void**)&attn, g_attn);
    float* Wf;   cudaGetSymbolAddress((void**)&Wf,   g_Wf);
    float* WoR;  cudaGetSymbolAddress((void**)&WoR,  g_WoR);
    float* bf;   cudaGetSymbolAddress((void**)&bf,   g_bf);
    float* xr;   cudaGetSymbolAddress((void**)&xr,   g_xr);

    build_T_kernel<<<64, 64>>>(diag, alpha);
    {
        dim3 grid((QKV_N + 255)/256, EMB);
        fold_w_kernel<<<grid, 256>>>(Wqkv);
        fold_b_kernel<<<(QKV_N + 255)/256, 256>>>(bqkv, bias_h);
        int n4x = M_ROWS*EMB/4;
        rna_kernel<<<(n4x + 255)/256, 256>>>(x, xr, n4x);
        int n4w = EMB*EMB/4;
        rna_kernel<<<(n4w + 255)/256, 256>>>(Wout, WoR, n4w);
    }

    cudaFuncSetAttribute(gemm_tf32_kernel,
                         cudaFuncAttributeMaxDynamicSharedMemorySize, GEMM_SMEM);
    {   // QKV GEMM: [4096,1024] @ [1024,3072], output RNA'd
        dim3 grid(QKV_N/256, M_ROWS/128);
        gemm_tf32_kernel<<<grid, 256, GEMM_SMEM>>>(xr, Wf, bf, qkv,
                                                   M_ROWS, QKV_N, EMB, 1);
    }
    {   // attention
        cudaFuncSetAttribute(attn_tf32_kernel,
                             cudaFuncAttributeMaxDynamicSharedMemorySize, ATTN_SMEM);
        dim3 grid(BATCH*NHEAD, SEQ/128);
        attn_tf32_kernel<<<grid, 256, ATTN_SMEM>>>(qkv, mask, attn);
    }
    {   // output projection: [4096,1024] @ [1024,1024], exact fp32 out
        dim3 grid(EMB/256, M_ROWS/128);
        gemm_tf32_kernel<<<grid, 256, GEMM_SMEM>>>(attn, WoR, bout, out,
                                                   M_ROWS, EMB, EMB, 0);
    }
}

// round 6
// speedup vs baseline: 4.4992x; 1.0895x over previous
#include <cuda_runtime.h>
#include <cuda_bf16.h>
#include <cstdint>
#include <math.h>

#define BATCH 2
#define SEQ   2048
#define EMB   1024
#define NHEAD 16
#define HDIM  64
#define M_ROWS (BATCH*SEQ)      // 4096
#define QKV_N  (3*EMB)          // 3072

// ---------------- scratch (device globals, no allocation) ----------------
__device__ float g_T[HDIM*HDIM];
__device__ float g_Wf[EMB*QKV_N];                // folded + RNA-tf32
__device__ float g_WoR[(size_t)EMB*EMB];         // RNA(Wout)
__device__ float g_bf[QKV_N];
__device__ float g_xr[(size_t)M_ROWS*EMB];       // RNA(x)
__device__ float g_qkv[(size_t)M_ROWS*QKV_N];    // RNA'd by GEMM epilogue
__device__ float g_attn[(size_t)M_ROWS*EMB];     // RNA'd by attn epilogue

__device__ __forceinline__ unsigned f2tf(float f) {
    unsigned u;
    asm("cvt.rna.tf32.f32 %0, %1;" : "=r"(u) : "f"(f));
    return u;
}
__device__ __forceinline__ float rnaf(float f) { return __uint_as_float(f2tf(f)); }

__device__ __forceinline__ uint32_t smem_u32(const void* p) {
    uint32_t a;
    asm("{ .reg .u64 t; cvta.to.shared.u64 t, %1; cvt.u32.u64 %0, t; }"
        : "=r"(a) : "l"(p));
    return a;
}

__device__ __forceinline__ void cp16(uint32_t dst, const void* src) {
    asm volatile("cp.async.cg.shared.global [%0], [%1], 16;" :: "r"(dst), "l"(src));
}
#define CP_COMMIT() asm volatile("cp.async.commit_group;" ::: "memory")
#define CP_WAIT(n)  asm volatile("cp.async.wait_group %0;" :: "n"(n) : "memory")

__device__ __forceinline__ void mma_tf32(float c[4],
                                         unsigned a0, unsigned a1, unsigned a2, unsigned a3,
                                         unsigned b0, unsigned b1) {
    asm volatile(
        "mma.sync.aligned.m16n8k8.row.col.f32.tf32.tf32.f32 "
        "{%0,%1,%2,%3}, {%4,%5,%6,%7}, {%8,%9}, {%0,%1,%2,%3};"
        : "+f"(c[0]), "+f"(c[1]), "+f"(c[2]), "+f"(c[3])
        : "r"(a0), "r"(a1), "r"(a2), "r"(a3), "r"(b0), "r"(b1));
}

// ---------------- build T = I + (alpha/64) * H diag H --------------------
__global__ void build_T_kernel(const float* __restrict__ diag,
                               const float* __restrict__ alpha_p) {
    int i = blockIdx.x, j = threadIdx.x;
    float a = alpha_p[0] * (1.0f / 64.0f);
    int ij = i ^ j;
    float acc = 0.f;
    #pragma unroll
    for (int k = 0; k < 64; k++)
        acc += diag[k] * ((__popc(ij & k) & 1) ? -1.f : 1.f);
    g_T[i*64 + j] = a * acc + ((i == j) ? 1.f : 0.f);
}

// ---------------- fold T into QKV weights (emit RNA-tf32) ----------------
__global__ void fold_w_kernel(const float* __restrict__ W) {
    int c = blockIdx.x * blockDim.x + threadIdx.x;
    int e = blockIdx.y;
    if (c >= QKV_N) return;
    size_t row = (size_t)e * QKV_N;
    if (c < 2*EMB) {
        int j = c & 63;
        int base = c - j;
        float acc = 0.f;
        #pragma unroll 8
        for (int d = 0; d < 64; d++)
            acc += W[row + base + d] * g_T[d*64 + j];
        g_Wf[row + c] = rnaf(acc);
    } else {
        g_Wf[row + c] = rnaf(W[row + c]);
    }
}

__global__ void fold_b_kernel(const float* __restrict__ bqkv,
                              const float* __restrict__ bias_h) {
    int c = blockIdx.x * blockDim.x + threadIdx.x;
    if (c >= QKV_N) return;
    if (c < 2*EMB) {
        int j = c & 63;
        int base = c - j;
        float acc = bias_h[j];
        #pragma unroll 8
        for (int d = 0; d < 64; d++)
            acc += bqkv[base + d] * g_T[d*64 + j];
        g_bf[c] = acc;
    } else {
        g_bf[c] = bqkv[c];
    }
}

// ---------------- elementwise RNA-to-tf32 ---------------------------------
__global__ void rna_kernel(const float* __restrict__ in, float* __restrict__ out, int n4) {
    int i = blockIdx.x * blockDim.x + threadIdx.x;
    if (i >= n4) return;
    float4 v = ((const float4*)in)[i];
    v.x = rnaf(v.x); v.y = rnaf(v.y); v.z = rnaf(v.z); v.w = rnaf(v.w);
    ((float4*)out)[i] = v;
}

// ---------------- tf32 GEMM: C = A@B + bias, cp.async 3-stage -------------
#define AP2 20
#define BP2 264
#define ASTG (128*AP2)
#define BSTG (16*BP2)
#define GSTG (ASTG + BSTG)
#define GEMM_SMEM (3*GSTG*4)
__global__ __launch_bounds__(256, 1)
void gemm_tf32_kernel(const float* __restrict__ A,
                      const float* __restrict__ B,
                      const float* __restrict__ bias,
                      float* __restrict__ C,
                      int M, int N, int K, int roundOut) {
    extern __shared__ unsigned sh[];
    uint32_t shA = smem_u32(sh);

    int tid = threadIdx.x;
    int warp = tid >> 5, lane = tid & 31;
    int tig = lane & 3, gid = lane >> 2;
    int warpM = warp & 1, warpN = warp >> 1;
    int m0 = blockIdx.y * 128;
    int n0 = blockIdx.x * 256;

    float c[4][8][4];
    #pragma unroll
    for (int mf = 0; mf < 4; mf++)
        #pragma unroll
        for (int nf = 0; nf < 8; nf++)
            #pragma unroll
            for (int j = 0; j < 4; j++) c[mf][nf][j] = 0.f;

    int nk = K / 16;

    auto issue = [&](int s, int k0) {
        uint32_t base = shA + (uint32_t)s * GSTG * 4;
        #pragma unroll
        for (int i = 0; i < 2; i++) {
            int li = tid + i*256;
            int row = li >> 2, kq = li & 3;
            cp16(base + (row*AP2 + kq*4)*4, A + (size_t)(m0 + row)*K + k0 + kq*4);
        }
        #pragma unroll
        for (int i = 0; i < 4; i++) {
            int li = tid + i*256;
            int kr = li >> 6, nq = li & 63;
            cp16(base + (ASTG + kr*BP2 + nq*4)*4, B + (size_t)(k0 + kr)*N + n0 + nq*4);
        }
        CP_COMMIT();
    };

    issue(0, 0);
    issue(1, 16);

    for (int kt = 0; kt < nk; kt++) {
        if (kt + 2 < nk) {
            issue((kt + 2) % 3, (kt + 2) * 16);
            CP_WAIT(2);
        } else if (kt + 1 < nk) {
            CP_WAIT(1);
        } else {
            CP_WAIT(0);
        }
        __syncthreads();

        unsigned* Ab = sh + (kt % 3) * GSTG;
        unsigned* Bb = Ab + ASTG;

        #pragma unroll
        for (int kk = 0; kk < 16; kk += 8) {
            unsigned af[4][4];
            #pragma unroll
            for (int mf = 0; mf < 4; mf++) {
                int m = warpM*64 + mf*16 + gid;
                af[mf][0] = Ab[m*AP2 + kk + tig];
                af[mf][1] = Ab[(m+8)*AP2 + kk + tig];
                af[mf][2] = Ab[m*AP2 + kk + tig + 4];
                af[mf][3] = Ab[(m+8)*AP2 + kk + tig + 4];
            }
            unsigned bf[8][2];
            #pragma unroll
            for (int nf = 0; nf < 8; nf++) {
                int n = warpN*64 + nf*8 + gid;
                bf[nf][0] = Bb[(kk+tig  )*BP2 + n];
                bf[nf][1] = Bb[(kk+tig+4)*BP2 + n];
            }
            #pragma unroll
            for (int mf = 0; mf < 4; mf++)
                #pragma unroll
                for (int nf = 0; nf < 8; nf++)
                    mma_tf32(c[mf][nf], af[mf][0], af[mf][1], af[mf][2], af[mf][3],
                             bf[nf][0], bf[nf][1]);
        }
        __syncthreads();
    }

    #pragma unroll
    for (int mf = 0; mf < 4; mf++) {
        int row = m0 + warpM*64 + mf*16 + gid;
        #pragma unroll
        for (int nf = 0; nf < 8; nf++) {
            int col = n0 + warpN*64 + nf*8 + 2*tig;
            float b0 = bias[col], b1 = bias[col+1];
            float v00 = c[mf][nf][0] + b0, v01 = c[mf][nf][1] + b1;
            float v10 = c[mf][nf][2] + b0, v11 = c[mf][nf][3] + b1;
            if (roundOut) { v00 = rnaf(v00); v01 = rnaf(v01); v10 = rnaf(v10); v11 = rnaf(v11); }
            *(float2*)&C[(size_t)row * N + col]     = make_float2(v00, v01);
            *(float2*)&C[(size_t)(row+8) * N + col] = make_float2(v10, v11);
        }
    }
}

// ---------------- flash attention, tf32, shfl-P, 2 CTAs/SM ----------------
// Bq=128, 256 threads = 8 warps; warp owns S rows 16w..16w+15.
// P never goes to smem: PV A-fragments built from the S C-fragments via shfl.
// smem: Q 128x68 + K 2x64x68 + V 2x64x72 + masks = ~107KB -> 2 CTAs/SM.
#define QP 68
#define VP 72
#define KSTG (64*QP)
#define VSTG (64*VP)
#define ATTN_SMEM ((128*QP + 2*KSTG + 2*VSTG)*4 + 2*64*4)
__global__ __launch_bounds__(256, 2)
void attn_tf32_kernel(const float* __restrict__ qkv,
                      const int* __restrict__ mask,
                      float* __restrict__ out) {
    extern __shared__ unsigned smU[];
    unsigned* Qs = smU;                     // [128][68]
    unsigned* Ks = Qs + 128*QP;             // [2][64][68]
    unsigned* Vs = Ks + 2*KSTG;             // [2][64][72]
    int*      Ms = (int*)(Vs + 2*VSTG);     // [2][64]

    uint32_t kA = smem_u32(Ks);
    uint32_t vA = smem_u32(Vs);
    uint32_t mA = smem_u32(Ms);

    int bh = blockIdx.x;
    int b = bh >> 4, h = bh & 15;
    int q0 = blockIdx.y * 128;

    int tid = threadIdx.x;
    int warp = tid >> 5, lane = tid & 31;
    int tig = lane & 3, gid = lane >> 2;
    int row0 = warp*16 + gid, row1 = row0 + 8;
    int srcL = (gid << 2) | (tig >> 1);
    int srcH = srcL + 2;
    bool odd = (tig & 1);

    const size_t rs = QKV_N;
    const float* qbase = qkv + (size_t)(b*SEQ)*rs + h*HDIM;
    const float* kbase = qbase + EMB;
    const float* vbase = qbase + 2*EMB;
    const int*   mrow  = mask + b*SEQ;

    auto issue = [&](int s, int k0) {
        #pragma unroll
        for (int i = 0; i < 4; i++) {
            int li = tid + i*256;
            int r = li >> 4, dq = (li & 15) * 4;
            cp16(kA + (s*KSTG + r*QP + dq)*4, kbase + (size_t)(k0 + r)*rs + dq);
            cp16(vA + (s*VSTG + r*VP + dq)*4, vbase + (size_t)(k0 + r)*rs + dq);
        }
        if (tid < 16) cp16(mA + s*256 + tid*16, mrow + k0 + tid*4);
        CP_COMMIT();
    };

    // load Q tile (values already tf32-rounded by QKV GEMM epilogue)
    #pragma unroll
    for (int i = 0; i < 8; i++) {
        int li = tid + i*256;
        int r = li >> 4, dq = (li & 15) * 4;
        uint4 v = *(const uint4*)&qbase[(size_t)(q0 + r)*rs + dq];
        *(uint4*)&Qs[r*QP + dq] = v;
    }

    issue(0, 0);
    issue(1, 64);

    float o[8][4];
    #pragma unroll
    for (int nf = 0; nf < 8; nf++)
        #pragma unroll
        for (int j = 0; j < 4; j++) o[nf][j] = 0.f;
    float m0r = -1e30f, m1r = -1e30f, l0 = 0.f, l1 = 0.f;

    const int NT = SEQ / 64;
    for (int kt = 0; kt < NT; kt++) {
        int st = kt & 1;
        if (kt + 1 < NT) { CP_WAIT(1); } else { CP_WAIT(0); }
        __syncthreads();

        unsigned* Kb = Ks + st*KSTG;
        unsigned* Vb = Vs + st*VSTG;
        int*      Mb = Ms + st*64;

        // S = Q K^T
        float s[8][4];
        #pragma unroll
        for (int nf = 0; nf < 8; nf++)
            #pragma unroll
            for (int j = 0; j < 4; j++) s[nf][j] = 0.f;
        #pragma unroll
        for (int kk = 0; kk < 64; kk += 8) {
            unsigned a0 = Qs[row0*QP + kk + tig];
            unsigned a1 = Qs[row1*QP + kk + tig];
            unsigned a2 = Qs[row0*QP + kk + tig + 4];
            unsigned a3 = Qs[row1*QP + kk + tig + 4];
            #pragma unroll
            for (int nf = 0; nf < 8; nf++) {
                unsigned b0 = Kb[(nf*8 + gid)*QP + kk + tig];
                unsigned b1 = Kb[(nf*8 + gid)*QP + kk + tig + 4];
                mma_tf32(s[nf], a0, a1, a2, a3, b0, b1);
            }
        }

        #pragma unroll
        for (int nf = 0; nf < 8; nf++) {
            int col = nf*8 + 2*tig;
            int mv0 = Mb[col], mv1 = Mb[col+1];
            s[nf][0] = mv0 ? s[nf][0]*0.125f : -1e30f;
            s[nf][1] = mv1 ? s[nf][1]*0.125f : -1e30f;
            s[nf][2] = mv0 ? s[nf][2]*0.125f : -1e30f;
            s[nf][3] = mv1 ? s[nf][3]*0.125f : -1e30f;
        }

        float rm0 = -1e30f, rm1 = -1e30f;
        #pragma unroll
        for (int nf = 0; nf < 8; nf++) {
            rm0 = fmaxf(rm0, fmaxf(s[nf][0], s[nf][1]));
            rm1 = fmaxf(rm1, fmaxf(s[nf][2], s[nf][3]));
        }
        rm0 = fmaxf(rm0, __shfl_xor_sync(0xffffffffu, rm0, 1));
        rm0 = fmaxf(rm0, __shfl_xor_sync(0xffffffffu, rm0, 2));
        rm1 = fmaxf(rm1, __shfl_xor_sync(0xffffffffu, rm1, 1));
        rm1 = fmaxf(rm1, __shfl_xor_sync(0xffffffffu, rm1, 2));

        float mn0 = fmaxf(m0r, rm0), mn1 = fmaxf(m1r, rm1);
        float sc0 = __expf(m0r - mn0), sc1 = __expf(m1r - mn1);
        m0r = mn0; m1r = mn1;

        float rs0 = 0.f, rs1 = 0.f;
        #pragma unroll
        for (int nf = 0; nf < 8; nf++) {
            s[nf][0] = __expf(s[nf][0] - mn0);
            s[nf][1] = __expf(s[nf][1] - mn0);
            s[nf][2] = __expf(s[nf][2] - mn1);
            s[nf][3] = __expf(s[nf][3] - mn1);
            rs0 += s[nf][0] + s[nf][1];
            rs1 += s[nf][2] + s[nf][3];
        }
        rs0 += __shfl_xor_sync(0xffffffffu, rs0, 1);
        rs0 += __shfl_xor_sync(0xffffffffu, rs0, 2);
        rs1 += __shfl_xor_sync(0xffffffffu, rs1, 1);
        rs1 += __shfl_xor_sync(0xffffffffu, rs1, 2);
        l0 = l0*sc0 + rs0;
        l1 = l1*sc1 + rs1;

        #pragma unroll
        for (int nf = 0; nf < 8; nf++) {
            o[nf][0] *= sc0; o[nf][1] *= sc0;
            o[nf][2] *= sc1; o[nf][3] *= sc1;
            // round P to tf32 bits (mma operand)
            s[nf][0] = rnaf(s[nf][0]); s[nf][1] = rnaf(s[nf][1]);
            s[nf][2] = rnaf(s[nf][2]); s[nf][3] = rnaf(s[nf][3]);
        }

        // O += P @ V ; A-fragments of P gathered via shfl from S C-fragments.
        // P[row][c]: c = kk+tig lives in lane (gid, tig>>1(+2)), component (tig&1).
        #pragma unroll
        for (int kk = 0; kk < 64; kk += 8) {
            int nfs = kk >> 3;
            float e00 = __shfl_sync(0xffffffffu, s[nfs][0], srcL);
            float e01 = __shfl_sync(0xffffffffu, s[nfs][1], srcL);
            float e10 = __shfl_sync(0xffffffffu, s[nfs][2], srcL);
            float e11 = __shfl_sync(0xffffffffu, s[nfs][3], srcL);
            float f00 = __shfl_sync(0xffffffffu, s[nfs][0], srcH);
            float f01 = __shfl_sync(0xffffffffu, s[nfs][1], srcH);
            float f10 = __shfl_sync(0xffffffffu, s[nfs][2], srcH);
            float f11 = __shfl_sync(0xffffffffu, s[nfs][3], srcH);
            unsigned a0 = __float_as_uint(odd ? e01 : e00);
            unsigned a1 = __float_as_uint(odd ? e11 : e10);
            unsigned a2 = __float_as_uint(odd ? f01 : f00);
            unsigned a3 = __float_as_uint(odd ? f11 : f10);
            #pragma unroll
            for (int nf = 0; nf < 8; nf++) {
                unsigned b0 = Vb[(kk + tig)*VP + nf*8 + gid];
                unsigned b1 = Vb[(kk + tig + 4)*VP + nf*8 + gid];
                mma_tf32(o[nf], a0, a1, a2, a3, b0, b1);
            }
        }
        __syncthreads();
        if (kt + 2 < NT) issue(st, (kt + 2) * 64);
    }

    // epilogue: normalize + RNA (consumed by out-proj GEMM)
    float inv0 = 1.f / l0, inv1 = 1.f / l1;
    #pragma unroll
    for (int nf = 0; nf < 8; nf++) {
        int col = nf*8 + 2*tig;
        size_t orow0 = (size_t)(b*SEQ + q0 + row0) * EMB + h*HDIM + col;
        size_t orow1 = (size_t)(b*SEQ + q0 + row1) * EMB + h*HDIM + col;
        *(float2*)&out[orow0] = make_float2(rnaf(o[nf][0]*inv0), rnaf(o[nf][1]*inv0));
        *(float2*)&out[orow1] = make_float2(rnaf(o[nf][2]*inv1), rnaf(o[nf][3]*inv1));
    }
}

// ---------------- launch ---------------------------------------------------
extern "C" void kernel_launch(void* const* d_in, const int* in_sizes, int n_in,
                              void* d_out, int out_size) {
    const float* x      = (const float*)d_in[0];
    const int*   mask   = (const int*)  d_in[1];
    const float* Wqkv   = (const float*)d_in[2];
    const float* bqkv   = (const float*)d_in[3];
    const float* Wout   = (const float*)d_in[4];
    const float* bout   = (const float*)d_in[5];
    const float* diag   = (const float*)d_in[6];
    const float* alpha  = (const float*)d_in[7];
    const float* bias_h = (const float*)d_in[8];
    float* out = (float*)d_out;

    float* qkv;  cudaGetSymbolAddress((void**)&qkv,  g_qkv);
    float* attn; cudaGetSymbolAddress((void**)&attn, g_attn);
    float* Wf;   cudaGetSymbolAddress((void**)&Wf,   g_Wf);
    float* WoR;  cudaGetSymbolAddress((void**)&WoR,  g_WoR);
    float* bf;   cudaGetSymbolAddress((void**)&bf,   g_bf);
    float* xr;   cudaGetSymbolAddress((void**)&xr,   g_xr);

    build_T_kernel<<<64, 64>>>(diag, alpha);
    {
        dim3 grid((QKV_N + 255)/256, EMB);
        fold_w_kernel<<<grid, 256>>>(Wqkv);
        fold_b_kernel<<<(QKV_N + 255)/256, 256>>>(bqkv, bias_h);
        int n4x = M_ROWS*EMB/4;
        rna_kernel<<<(n4x + 255)/256, 256>>>(x, xr, n4x);
        int n4w = EMB*EMB/4;
        rna_kernel<<<(n4w + 255)/256, 256>>>(Wout, WoR, n4w);
    }

    cudaFuncSetAttribute(gemm_tf32_kernel,
                         cudaFuncAttributeMaxDynamicSharedMemorySize, GEMM_SMEM);
    {   // QKV GEMM: [4096,1024] @ [1024,3072], output RNA'd
        dim3 grid(QKV_N/256, M_ROWS/128);
        gemm_tf32_kernel<<<grid, 256, GEMM_SMEM>>>(xr, Wf, bf, qkv,
                                                   M_ROWS, QKV_N, EMB, 1);
    }
    {   // attention
        cudaFuncSetAttribute(attn_tf32_kernel,
                             cudaFuncAttributeMaxDynamicSharedMemorySize, ATTN_SMEM);
        dim3 grid(BATCH*NHEAD, SEQ/128);
        attn_tf32_kernel<<<grid, 256, ATTN_SMEM>>>(qkv, mask, attn);
    }
    {   // output projection: [4096,1024] @ [1024,1024], exact fp32 out
        dim3 grid(EMB/256, M_ROWS/128);
        gemm_tf32_kernel<<<grid, 256, GEMM_SMEM>>>(attn, WoR, bout, out,
                                                   M_ROWS, EMB, EMB, 0);
    }
}